// round 1
// baseline (speedup 1.0000x reference)
#include <cuda_runtime.h>
#include <cuda_bf16.h>

#define NMAX 50000
#define DIN 128
#define DHID 128
#define DOUT 64

__device__ float g_dinv[NMAX];           // deg -> rsqrt(deg)
__device__ float g_h[NMAX * DHID];       // dinv[i] * (x[i] @ W1)
__device__ float g_acc1[NMAX * DHID];    // scatter accumulator layer 1
__device__ float g_h2[NMAX * DOUT];      // dinv[i] * (relu1[i] @ W2)
__device__ float g_acc2[NMAX * DOUT];    // scatter accumulator layer 2
__device__ int   g_is64;                 // edge_index dtype flag

__device__ __forceinline__ void red_add4(float* addr, float4 v) {
    asm volatile("red.global.add.v4.f32 [%0], {%1,%2,%3,%4};"
                 :: "l"(addr), "f"(v.x), "f"(v.y), "f"(v.z), "f"(v.w)
                 : "memory");
}

__device__ __forceinline__ int edge_at(const void* ei, int idx) {
    if (g_is64) return (int)((const long long*)ei)[idx];
    return ((const int*)ei)[idx];
}

// ---------------------------------------------------------------------------
// dtype detection: if int64, every odd 32-bit word of the first 64 entries is 0
// ---------------------------------------------------------------------------
__global__ void k_detect(const unsigned int* p) {
    int ok = 1;
    for (int i = 0; i < 64; i++)
        if (p[2 * i + 1] != 0u) ok = 0;
    g_is64 = ok;
}

__global__ void k_deg_init(int n) {
    int i = blockIdx.x * blockDim.x + threadIdx.x;
    if (i < n) g_dinv[i] = 1.0f;  // self-loop
}

__global__ void k_deg(const void* ei, int E) {
    int e = blockIdx.x * blockDim.x + threadIdx.x;
    if (e >= E) return;
    int dst = edge_at(ei, E + e);
    atomicAdd(&g_dinv[dst], 1.0f);
}

__global__ void k_rsqrt(int n) {
    int i = blockIdx.x * blockDim.x + threadIdx.x;
    if (i < n) g_dinv[i] = rsqrtf(g_dinv[i]);
}

// ---------------------------------------------------------------------------
// GEMM1: g_h[i][:] = dinv[i] * (x[i] @ W1);  g_acc1 = g_h (self-loop init)
// Tile 128 rows x 128 cols, 256 threads, each thread 16 rows x 4 cols.
// ---------------------------------------------------------------------------
__global__ __launch_bounds__(256) void k_gemm1(const float* __restrict__ x,
                                               const float* __restrict__ W,
                                               int n) {
    __shared__ float xs[16][DIN + 1];   // [k][row]
    __shared__ float ws[16][DIN];       // [k][col]
    const int tx = threadIdx.x & 31;    // col group: cols 4*tx..4*tx+3
    const int ty = threadIdx.x >> 5;    // row lane: rows ty + 8*r
    const int row0 = blockIdx.x * 128;

    float acc[16][4];
#pragma unroll
    for (int r = 0; r < 16; r++) { acc[r][0]=0.f; acc[r][1]=0.f; acc[r][2]=0.f; acc[r][3]=0.f; }

    for (int kc = 0; kc < DIN; kc += 16) {
        // x tile (transpose into [k][row])
#pragma unroll
        for (int it = 0; it < 2; it++) {
            int t  = threadIdx.x + it * 256;
            int r  = t >> 2;            // 0..127
            int kq = (t & 3) * 4;       // 0,4,8,12
            float4 v = make_float4(0.f, 0.f, 0.f, 0.f);
            if (row0 + r < n)
                v = *(const float4*)&x[(size_t)(row0 + r) * DIN + kc + kq];
            xs[kq + 0][r] = v.x; xs[kq + 1][r] = v.y;
            xs[kq + 2][r] = v.z; xs[kq + 3][r] = v.w;
        }
        // W tile
#pragma unroll
        for (int it = 0; it < 2; it++) {
            int t = threadIdx.x + it * 256;
            int k = t >> 5;             // 0..15
            int c = (t & 31) * 4;
            *(float4*)&ws[k][c] = *(const float4*)&W[(size_t)(kc + k) * DIN + c];
        }
        __syncthreads();
#pragma unroll
        for (int k = 0; k < 16; k++) {
            float4 w4 = *(float4*)&ws[k][tx * 4];
#pragma unroll
            for (int r = 0; r < 16; r++) {
                float xv = xs[k][ty + r * 8];
                acc[r][0] += xv * w4.x;
                acc[r][1] += xv * w4.y;
                acc[r][2] += xv * w4.z;
                acc[r][3] += xv * w4.w;
            }
        }
        __syncthreads();
    }
#pragma unroll
    for (int r = 0; r < 16; r++) {
        int row = row0 + ty + r * 8;
        if (row < n) {
            float d = g_dinv[row];
            float4 o = make_float4(acc[r][0]*d, acc[r][1]*d, acc[r][2]*d, acc[r][3]*d);
            *(float4*)&g_h[(size_t)row * DHID + tx * 4]    = o;
            *(float4*)&g_acc1[(size_t)row * DHID + tx * 4] = o;
        }
    }
}

// ---------------------------------------------------------------------------
// scatter1: acc1[dst] += h[src]  (one warp per edge, float4 per lane)
// ---------------------------------------------------------------------------
__global__ void k_scatter1(const void* ei, int E) {
    int idx = blockIdx.x * blockDim.x + threadIdx.x;
    if (idx >= E * 32) return;
    int e = idx >> 5;
    int l = idx & 31;
    int src = edge_at(ei, e);
    int dst = edge_at(ei, E + e);
    float4 v = *(const float4*)&g_h[(size_t)src * DHID + l * 4];
    red_add4(&g_acc1[(size_t)dst * DHID + l * 4], v);
}

// ---------------------------------------------------------------------------
// GEMM2: in[i][k] = relu(dinv[i]*acc1[i][k] + b1[k]);
//        g_h2[i][:] = dinv[i] * (in[i] @ W2);  g_acc2 = g_h2
// Tile 128 rows x 64 cols, 256 threads, each thread 8 rows x 4 cols.
// ---------------------------------------------------------------------------
__global__ __launch_bounds__(256) void k_gemm2(const float* __restrict__ b1,
                                               const float* __restrict__ W,
                                               int n) {
    __shared__ float xs[16][128 + 1];   // [k][row]
    __shared__ float ws[16][DOUT];      // [k][col]
    const int tx = threadIdx.x & 15;    // cols 4*tx..4*tx+3 (64 total)
    const int ty = threadIdx.x >> 4;    // 0..15; rows ty + 16*r
    const int row0 = blockIdx.x * 128;

    float acc[8][4];
#pragma unroll
    for (int r = 0; r < 8; r++) { acc[r][0]=0.f; acc[r][1]=0.f; acc[r][2]=0.f; acc[r][3]=0.f; }

    for (int kc = 0; kc < DHID; kc += 16) {
        // input tile with fused (dinv*acc1 + b1) -> relu, transposed store
#pragma unroll
        for (int it = 0; it < 2; it++) {
            int t  = threadIdx.x + it * 256;
            int r  = t >> 2;
            int kq = (t & 3) * 4;
            float4 v = make_float4(0.f, 0.f, 0.f, 0.f);
            if (row0 + r < n) {
                float d = g_dinv[row0 + r];
                float4 a  = *(const float4*)&g_acc1[(size_t)(row0 + r) * DHID + kc + kq];
                float4 bb = *(const float4*)&b1[kc + kq];
                v.x = fmaxf(d * a.x + bb.x, 0.f);
                v.y = fmaxf(d * a.y + bb.y, 0.f);
                v.z = fmaxf(d * a.z + bb.z, 0.f);
                v.w = fmaxf(d * a.w + bb.w, 0.f);
            }
            xs[kq + 0][r] = v.x; xs[kq + 1][r] = v.y;
            xs[kq + 2][r] = v.z; xs[kq + 3][r] = v.w;
        }
        // W2 tile: 16 x 64 floats, 1 float4 per thread
        {
            int t = threadIdx.x;
            int k = t >> 4;
            int c = (t & 15) * 4;
            *(float4*)&ws[k][c] = *(const float4*)&W[(size_t)(kc + k) * DOUT + c];
        }
        __syncthreads();
#pragma unroll
        for (int k = 0; k < 16; k++) {
            float4 w4 = *(float4*)&ws[k][tx * 4];
#pragma unroll
            for (int r = 0; r < 8; r++) {
                float xv = xs[k][ty + r * 16];
                acc[r][0] += xv * w4.x;
                acc[r][1] += xv * w4.y;
                acc[r][2] += xv * w4.z;
                acc[r][3] += xv * w4.w;
            }
        }
        __syncthreads();
    }
#pragma unroll
    for (int r = 0; r < 8; r++) {
        int row = row0 + ty + r * 16;
        if (row < n) {
            float d = g_dinv[row];
            float4 o = make_float4(acc[r][0]*d, acc[r][1]*d, acc[r][2]*d, acc[r][3]*d);
            *(float4*)&g_h2[(size_t)row * DOUT + tx * 4]   = o;
            *(float4*)&g_acc2[(size_t)row * DOUT + tx * 4] = o;
        }
    }
}

// ---------------------------------------------------------------------------
// scatter2: acc2[dst] += h2[src]  (16 lanes per edge, float4 per lane)
// ---------------------------------------------------------------------------
__global__ void k_scatter2(const void* ei, int E) {
    int idx = blockIdx.x * blockDim.x + threadIdx.x;
    if (idx >= E * 16) return;
    int e = idx >> 4;
    int l = idx & 15;
    int src = edge_at(ei, e);
    int dst = edge_at(ei, E + e);
    float4 v = *(const float4*)&g_h2[(size_t)src * DOUT + l * 4];
    red_add4(&g_acc2[(size_t)dst * DOUT + l * 4], v);
}

// ---------------------------------------------------------------------------
// finalize: out = dinv * acc2 + b2
// ---------------------------------------------------------------------------
__global__ void k_final(const float* __restrict__ b2, float* __restrict__ out, int n) {
    int idx = blockIdx.x * blockDim.x + threadIdx.x;
    if (idx >= n * 16) return;
    int row = idx >> 4;
    int c = (idx & 15) * 4;
    float d = g_dinv[row];
    float4 a  = *(const float4*)&g_acc2[(size_t)row * DOUT + c];
    float4 bb = *(const float4*)&b2[c];
    float4 o = make_float4(d*a.x + bb.x, d*a.y + bb.y, d*a.z + bb.z, d*a.w + bb.w);
    *(float4*)&out[(size_t)idx * 4] = o;
}

extern "C" void kernel_launch(void* const* d_in, const int* in_sizes, int n_in,
                              void* d_out, int out_size) {
    const float* x  = (const float*)d_in[0];
    const void*  ei = d_in[1];
    const float* W1 = (const float*)d_in[2];
    const float* b1 = (const float*)d_in[3];
    const float* W2 = (const float*)d_in[4];
    const float* b2 = (const float*)d_in[5];
    float* out = (float*)d_out;

    const int n = in_sizes[0] / DIN;
    const int E = in_sizes[1] / 2;

    k_detect<<<1, 1>>>((const unsigned int*)ei);
    k_deg_init<<<(n + 255) / 256, 256>>>(n);
    k_deg<<<(E + 255) / 256, 256>>>(ei, E);
    k_rsqrt<<<(n + 255) / 256, 256>>>(n);

    k_gemm1<<<(n + 127) / 128, 256>>>(x, W1, n);
    k_scatter1<<<(E * 32 + 255) / 256, 256>>>(ei, E);

    k_gemm2<<<(n + 127) / 128, 256>>>(b1, W2, n);
    k_scatter2<<<(E * 16 + 255) / 256, 256>>>(ei, E);

    k_final<<<(n * 16 + 255) / 256, 256>>>(b2, out, n);
}

// round 2
// speedup vs baseline: 1.3225x; 1.3225x over previous
#include <cuda_runtime.h>

#define NMAX 50000
#define EMAX 700000
#define DIN 128
#define DHID 128
#define DOUT 64

__device__ float g_dinv[NMAX];
__device__ int2  g_edge[EMAX];
__device__ float g_h[NMAX * DHID];
__device__ float g_acc1[NMAX * DHID];
__device__ float g_h2[NMAX * DOUT];
__device__ float g_acc2[NMAX * DOUT];
__device__ int   g_is64;

__device__ __forceinline__ void red_add4(float* addr, float4 v) {
    asm volatile("red.global.add.v4.f32 [%0], {%1,%2,%3,%4};"
                 :: "l"(addr), "f"(v.x), "f"(v.y), "f"(v.z), "f"(v.w)
                 : "memory");
}

__device__ __forceinline__ unsigned f2tf(float f) {
    unsigned u;
    asm("cvt.rna.tf32.f32 %0, %1;" : "=r"(u) : "f"(f));
    return u;
}

__device__ __forceinline__ void mma8(float* c, const unsigned* a, const unsigned* b) {
    asm volatile(
        "mma.sync.aligned.m16n8k8.row.col.f32.tf32.tf32.f32 "
        "{%0,%1,%2,%3},{%4,%5,%6,%7},{%8,%9},{%0,%1,%2,%3};"
        : "+f"(c[0]), "+f"(c[1]), "+f"(c[2]), "+f"(c[3])
        : "r"(a[0]), "r"(a[1]), "r"(a[2]), "r"(a[3]), "r"(b[0]), "r"(b[1]));
}

// ---------------------------------------------------------------------------
__global__ void k_detect(const unsigned int* p) {
    int ok = 1;
    for (int i = 0; i < 64; i++)
        if (p[2 * i + 1] != 0u) ok = 0;
    g_is64 = ok;
}

__global__ void k_deg_init(int n) {
    int i = blockIdx.x * blockDim.x + threadIdx.x;
    if (i < n) g_dinv[i] = 1.0f;  // self-loop
}

// convert edges to packed int2 + accumulate degree
__global__ void k_convert(const void* ei, int E) {
    int e = blockIdx.x * blockDim.x + threadIdx.x;
    if (e >= E) return;
    int src, dst;
    if (g_is64) {
        const long long* p = (const long long*)ei;
        src = (int)p[e]; dst = (int)p[E + e];
    } else {
        const int* p = (const int*)ei;
        src = p[e]; dst = p[E + e];
    }
    g_edge[e] = make_int2(src, dst);
    atomicAdd(&g_dinv[dst], 1.0f);
}

__global__ void k_rsqrt(int n) {
    int i = blockIdx.x * blockDim.x + threadIdx.x;
    if (i < n) g_dinv[i] = rsqrtf(g_dinv[i]);
}

// ---------------------------------------------------------------------------
// GEMM1 (tf32 MMA): g_h[i][:] = dinv[i] * (x[i] @ W1);  g_acc1 = g_h
// CTA tile 128x128, 8 warps (4m x 2n), warp tile 32x64.
// ---------------------------------------------------------------------------
__global__ __launch_bounds__(256) void k_gemm1(const float* __restrict__ x,
                                               const float* __restrict__ W,
                                               int n) {
    __shared__ unsigned xs[128][36];   // [row][k], pad 4 -> conflict-free frags
    __shared__ unsigned ws[32][132];   // [k][col], pad 4

    const int t = threadIdx.x;
    const int lane = t & 31;
    const int warp = t >> 5;
    const int wm = warp >> 1;          // 0..3
    const int wn = warp & 1;           // 0..1
    const int row0 = blockIdx.x * 128;

    float acc[2][8][4];
#pragma unroll
    for (int m = 0; m < 2; m++)
#pragma unroll
        for (int nn = 0; nn < 8; nn++)
#pragma unroll
            for (int j = 0; j < 4; j++) acc[m][nn][j] = 0.f;

    for (int kc = 0; kc < DIN; kc += 32) {
        // xs: 128x32 floats = 1024 float4
#pragma unroll
        for (int i = 0; i < 4; i++) {
            int idx = t + i * 256;
            int r = idx >> 3, c = (idx & 7) * 4;
            float4 v = make_float4(0.f, 0.f, 0.f, 0.f);
            if (row0 + r < n)
                v = *(const float4*)&x[(size_t)(row0 + r) * DIN + kc + c];
            xs[r][c + 0] = f2tf(v.x); xs[r][c + 1] = f2tf(v.y);
            xs[r][c + 2] = f2tf(v.z); xs[r][c + 3] = f2tf(v.w);
        }
        // ws: 32x128 floats = 1024 float4
#pragma unroll
        for (int i = 0; i < 4; i++) {
            int idx = t + i * 256;
            int k = idx >> 5, c = (idx & 31) * 4;
            float4 v = *(const float4*)&W[(size_t)(kc + k) * DHID + c];
            ws[k][c + 0] = f2tf(v.x); ws[k][c + 1] = f2tf(v.y);
            ws[k][c + 2] = f2tf(v.z); ws[k][c + 3] = f2tf(v.w);
        }
        __syncthreads();
#pragma unroll
        for (int ks = 0; ks < 4; ks++) {
            int k0 = ks * 8;
            unsigned a[2][4];
#pragma unroll
            for (int m = 0; m < 2; m++) {
                int r = wm * 32 + m * 16 + (lane >> 2);
                int kk = k0 + (lane & 3);
                a[m][0] = xs[r][kk];
                a[m][1] = xs[r + 8][kk];
                a[m][2] = xs[r][kk + 4];
                a[m][3] = xs[r + 8][kk + 4];
            }
#pragma unroll
            for (int nn = 0; nn < 8; nn++) {
                unsigned b[2];
                int c = wn * 64 + nn * 8 + (lane >> 2);
                b[0] = ws[k0 + (lane & 3)][c];
                b[1] = ws[k0 + (lane & 3) + 4][c];
                mma8(acc[0][nn], a[0], b);
                mma8(acc[1][nn], a[1], b);
            }
        }
        __syncthreads();
    }
    // epilogue: scale by dinv, write g_h and g_acc1
#pragma unroll
    for (int m = 0; m < 2; m++) {
#pragma unroll
        for (int h = 0; h < 2; h++) {
            int row = row0 + wm * 32 + m * 16 + (lane >> 2) + h * 8;
            if (row < n) {
                float d = g_dinv[row];
#pragma unroll
                for (int nn = 0; nn < 8; nn++) {
                    int col = wn * 64 + nn * 8 + (lane & 3) * 2;
                    float2 o;
                    o.x = acc[m][nn][h * 2 + 0] * d;
                    o.y = acc[m][nn][h * 2 + 1] * d;
                    *(float2*)&g_h[(size_t)row * DHID + col]    = o;
                    *(float2*)&g_acc1[(size_t)row * DHID + col] = o;
                }
            }
        }
    }
}

// ---------------------------------------------------------------------------
// scatter1: acc1[dst] += h[src]  (one warp per edge, float4 per lane)
// ---------------------------------------------------------------------------
__global__ void k_scatter1(int E) {
    int idx = blockIdx.x * blockDim.x + threadIdx.x;
    if (idx >= E * 32) return;
    int e = idx >> 5;
    int l = idx & 31;
    int2 ed = g_edge[e];
    float4 v = *(const float4*)&g_h[(size_t)ed.x * DHID + l * 4];
    red_add4(&g_acc1[(size_t)ed.y * DHID + l * 4], v);
}

// ---------------------------------------------------------------------------
// GEMM2 (tf32 MMA): in[i][k] = relu(dinv[i]*acc1[i][k] + b1[k]);
//                   g_h2 = dinv * (in @ W2);  g_acc2 = g_h2
// CTA tile 128x64, 8 warps (4m x 2n), warp tile 32x32.
// ---------------------------------------------------------------------------
__global__ __launch_bounds__(256) void k_gemm2(const float* __restrict__ b1,
                                               const float* __restrict__ W,
                                               int n) {
    __shared__ unsigned xs[128][36];
    __shared__ unsigned ws[32][68];

    const int t = threadIdx.x;
    const int lane = t & 31;
    const int warp = t >> 5;
    const int wm = warp >> 1;
    const int wn = warp & 1;
    const int row0 = blockIdx.x * 128;

    float acc[2][4][4];
#pragma unroll
    for (int m = 0; m < 2; m++)
#pragma unroll
        for (int nn = 0; nn < 4; nn++)
#pragma unroll
            for (int j = 0; j < 4; j++) acc[m][nn][j] = 0.f;

    for (int kc = 0; kc < DHID; kc += 32) {
        // xs with fused relu(dinv*acc1 + b1)
#pragma unroll
        for (int i = 0; i < 4; i++) {
            int idx = t + i * 256;
            int r = idx >> 3, c = (idx & 7) * 4;
            float4 v = make_float4(0.f, 0.f, 0.f, 0.f);
            if (row0 + r < n) {
                float d = g_dinv[row0 + r];
                float4 a4 = *(const float4*)&g_acc1[(size_t)(row0 + r) * DHID + kc + c];
                float4 b4 = *(const float4*)&b1[kc + c];
                v.x = fmaxf(d * a4.x + b4.x, 0.f);
                v.y = fmaxf(d * a4.y + b4.y, 0.f);
                v.z = fmaxf(d * a4.z + b4.z, 0.f);
                v.w = fmaxf(d * a4.w + b4.w, 0.f);
            }
            xs[r][c + 0] = f2tf(v.x); xs[r][c + 1] = f2tf(v.y);
            xs[r][c + 2] = f2tf(v.z); xs[r][c + 3] = f2tf(v.w);
        }
        // ws: 32x64 floats = 512 float4
#pragma unroll
        for (int i = 0; i < 2; i++) {
            int idx = t + i * 256;
            int k = idx >> 4, c = (idx & 15) * 4;
            float4 v = *(const float4*)&W[(size_t)(kc + k) * DOUT + c];
            ws[k][c + 0] = f2tf(v.x); ws[k][c + 1] = f2tf(v.y);
            ws[k][c + 2] = f2tf(v.z); ws[k][c + 3] = f2tf(v.w);
        }
        __syncthreads();
#pragma unroll
        for (int ks = 0; ks < 4; ks++) {
            int k0 = ks * 8;
            unsigned a[2][4];
#pragma unroll
            for (int m = 0; m < 2; m++) {
                int r = wm * 32 + m * 16 + (lane >> 2);
                int kk = k0 + (lane & 3);
                a[m][0] = xs[r][kk];
                a[m][1] = xs[r + 8][kk];
                a[m][2] = xs[r][kk + 4];
                a[m][3] = xs[r + 8][kk + 4];
            }
#pragma unroll
            for (int nn = 0; nn < 4; nn++) {
                unsigned b[2];
                int c = wn * 32 + nn * 8 + (lane >> 2);
                b[0] = ws[k0 + (lane & 3)][c];
                b[1] = ws[k0 + (lane & 3) + 4][c];
                mma8(acc[0][nn], a[0], b);
                mma8(acc[1][nn], a[1], b);
            }
        }
        __syncthreads();
    }
#pragma unroll
    for (int m = 0; m < 2; m++) {
#pragma unroll
        for (int h = 0; h < 2; h++) {
            int row = row0 + wm * 32 + m * 16 + (lane >> 2) + h * 8;
            if (row < n) {
                float d = g_dinv[row];
#pragma unroll
                for (int nn = 0; nn < 4; nn++) {
                    int col = wn * 32 + nn * 8 + (lane & 3) * 2;
                    float2 o;
                    o.x = acc[m][nn][h * 2 + 0] * d;
                    o.y = acc[m][nn][h * 2 + 1] * d;
                    *(float2*)&g_h2[(size_t)row * DOUT + col]   = o;
                    *(float2*)&g_acc2[(size_t)row * DOUT + col] = o;
                }
            }
        }
    }
}

// ---------------------------------------------------------------------------
// scatter2: acc2[dst] += h2[src]  (16 lanes per edge, float4 per lane)
// ---------------------------------------------------------------------------
__global__ void k_scatter2(int E) {
    int idx = blockIdx.x * blockDim.x + threadIdx.x;
    if (idx >= E * 16) return;
    int e = idx >> 4;
    int l = idx & 15;
    int2 ed = g_edge[e];
    float4 v = *(const float4*)&g_h2[(size_t)ed.x * DOUT + l * 4];
    red_add4(&g_acc2[(size_t)ed.y * DOUT + l * 4], v);
}

// ---------------------------------------------------------------------------
// finalize: out = dinv * acc2 + b2
// ---------------------------------------------------------------------------
__global__ void k_final(const float* __restrict__ b2, float* __restrict__ out, int n) {
    int idx = blockIdx.x * blockDim.x + threadIdx.x;
    if (idx >= n * 16) return;
    int row = idx >> 4;
    int c = (idx & 15) * 4;
    float d = g_dinv[row];
    float4 a  = *(const float4*)&g_acc2[(size_t)row * DOUT + c];
    float4 bb = *(const float4*)&b2[c];
    float4 o = make_float4(d * a.x + bb.x, d * a.y + bb.y, d * a.z + bb.z, d * a.w + bb.w);
    *(float4*)&out[(size_t)idx * 4] = o;
}

extern "C" void kernel_launch(void* const* d_in, const int* in_sizes, int n_in,
                              void* d_out, int out_size) {
    const float* x  = (const float*)d_in[0];
    const void*  ei = d_in[1];
    const float* W1 = (const float*)d_in[2];
    const float* b1 = (const float*)d_in[3];
    const float* W2 = (const float*)d_in[4];
    const float* b2 = (const float*)d_in[5];
    float* out = (float*)d_out;

    const int n = in_sizes[0] / DIN;
    const int E = in_sizes[1] / 2;

    k_detect<<<1, 1>>>((const unsigned int*)ei);
    k_deg_init<<<(n + 255) / 256, 256>>>(n);
    k_convert<<<(E + 255) / 256, 256>>>(ei, E);
    k_rsqrt<<<(n + 255) / 256, 256>>>(n);

    k_gemm1<<<(n + 127) / 128, 256>>>(x, W1, n);
    k_scatter1<<<(E * 32 + 255) / 256, 256>>>(E);

    k_gemm2<<<(n + 127) / 128, 256>>>(b1, W2, n);
    k_scatter2<<<(E * 16 + 255) / 256, 256>>>(E);

    k_final<<<(n * 16 + 255) / 256, 256>>>(b2, out, n);
}

// round 3
// speedup vs baseline: 2.0625x; 1.5596x over previous
#include <cuda_runtime.h>

#define NMAX 50000
#define BCAP 64
#define OVF_MAX 4096
#define DIN 128
#define DHID 128
#define DOUT 64

__device__ int   g_degi[NMAX];            // in-degree (no self-loop)
__device__ int   g_srcs[NMAX * BCAP];     // bucketed src lists per dst
__device__ int2  g_ovf[OVF_MAX];          // overflow edges (src,dst)
__device__ int   g_ovf_cnt;
__device__ float g_h[NMAX * DHID];        // dinv[i] * (x[i] @ W1)
__device__ float g_acc1[NMAX * DHID];
__device__ float g_h2[NMAX * DOUT];       // dinv[i] * (relu1[i] @ W2)
__device__ float g_acc2[NMAX * DOUT];
__device__ int   g_is64;

__device__ __forceinline__ unsigned f2tf(float f) {
    unsigned u;
    asm("cvt.rna.tf32.f32 %0, %1;" : "=r"(u) : "f"(f));
    return u;
}

__device__ __forceinline__ void mma8(float* c, const unsigned* a, const unsigned* b) {
    asm volatile(
        "mma.sync.aligned.m16n8k8.row.col.f32.tf32.tf32.f32 "
        "{%0,%1,%2,%3},{%4,%5,%6,%7},{%8,%9},{%0,%1,%2,%3};"
        : "+f"(c[0]), "+f"(c[1]), "+f"(c[2]), "+f"(c[3])
        : "r"(a[0]), "r"(a[1]), "r"(a[2]), "r"(a[3]), "r"(b[0]), "r"(b[1]));
}

__device__ __forceinline__ float dinv_of(int row) {
    return rsqrtf((float)(g_degi[row] + 1));
}

// ---------------------------------------------------------------------------
// init: zero degree counters + overflow counter; thread 0 detects edge dtype
// ---------------------------------------------------------------------------
__global__ void k_init(const unsigned int* p, int n) {
    int i = blockIdx.x * blockDim.x + threadIdx.x;
    if (i < n) g_degi[i] = 0;
    if (i == 0) {
        g_ovf_cnt = 0;
        int ok = 1;
        for (int j = 0; j < 64; j++)
            if (p[2 * j + 1] != 0u) ok = 0;
        g_is64 = ok;
    }
}

// ---------------------------------------------------------------------------
// convert: bucket edges by dst (counting degree via the same atomic)
// ---------------------------------------------------------------------------
__global__ void k_convert(const void* ei, int E) {
    int e = blockIdx.x * blockDim.x + threadIdx.x;
    if (e >= E) return;
    int src, dst;
    if (g_is64) {
        const long long* p = (const long long*)ei;
        src = (int)p[e]; dst = (int)p[E + e];
    } else {
        const int* p = (const int*)ei;
        src = p[e]; dst = p[E + e];
    }
    int slot = atomicAdd(&g_degi[dst], 1);
    if (slot < BCAP) {
        g_srcs[dst * BCAP + slot] = src;
    } else {
        int o = atomicAdd(&g_ovf_cnt, 1);
        if (o < OVF_MAX) g_ovf[o] = make_int2(src, dst);
    }
}

// ---------------------------------------------------------------------------
// GEMM1 (tf32 MMA): g_h[i][:] = dinv[i] * (x[i] @ W1)
// CTA tile 128x128, 8 warps (4m x 2n), warp tile 32x64.
// ---------------------------------------------------------------------------
__global__ __launch_bounds__(256) void k_gemm1(const float* __restrict__ x,
                                               const float* __restrict__ W,
                                               int n) {
    __shared__ unsigned xs[128][36];
    __shared__ unsigned ws[32][132];

    const int t = threadIdx.x;
    const int lane = t & 31;
    const int warp = t >> 5;
    const int wm = warp >> 1;
    const int wn = warp & 1;
    const int row0 = blockIdx.x * 128;

    float acc[2][8][4];
#pragma unroll
    for (int m = 0; m < 2; m++)
#pragma unroll
        for (int nn = 0; nn < 8; nn++)
#pragma unroll
            for (int j = 0; j < 4; j++) acc[m][nn][j] = 0.f;

    for (int kc = 0; kc < DIN; kc += 32) {
#pragma unroll
        for (int i = 0; i < 4; i++) {
            int idx = t + i * 256;
            int r = idx >> 3, c = (idx & 7) * 4;
            float4 v = make_float4(0.f, 0.f, 0.f, 0.f);
            if (row0 + r < n)
                v = *(const float4*)&x[(size_t)(row0 + r) * DIN + kc + c];
            xs[r][c + 0] = f2tf(v.x); xs[r][c + 1] = f2tf(v.y);
            xs[r][c + 2] = f2tf(v.z); xs[r][c + 3] = f2tf(v.w);
        }
#pragma unroll
        for (int i = 0; i < 4; i++) {
            int idx = t + i * 256;
            int k = idx >> 5, c = (idx & 31) * 4;
            float4 v = *(const float4*)&W[(size_t)(kc + k) * DHID + c];
            ws[k][c + 0] = f2tf(v.x); ws[k][c + 1] = f2tf(v.y);
            ws[k][c + 2] = f2tf(v.z); ws[k][c + 3] = f2tf(v.w);
        }
        __syncthreads();
#pragma unroll
        for (int ks = 0; ks < 4; ks++) {
            int k0 = ks * 8;
            unsigned a[2][4];
#pragma unroll
            for (int m = 0; m < 2; m++) {
                int r = wm * 32 + m * 16 + (lane >> 2);
                int kk = k0 + (lane & 3);
                a[m][0] = xs[r][kk];
                a[m][1] = xs[r + 8][kk];
                a[m][2] = xs[r][kk + 4];
                a[m][3] = xs[r + 8][kk + 4];
            }
#pragma unroll
            for (int nn = 0; nn < 8; nn++) {
                unsigned b[2];
                int c = wn * 64 + nn * 8 + (lane >> 2);
                b[0] = ws[k0 + (lane & 3)][c];
                b[1] = ws[k0 + (lane & 3) + 4][c];
                mma8(acc[0][nn], a[0], b);
                mma8(acc[1][nn], a[1], b);
            }
        }
        __syncthreads();
    }
#pragma unroll
    for (int m = 0; m < 2; m++) {
#pragma unroll
        for (int h = 0; h < 2; h++) {
            int row = row0 + wm * 32 + m * 16 + (lane >> 2) + h * 8;
            if (row < n) {
                float d = dinv_of(row);
#pragma unroll
                for (int nn = 0; nn < 8; nn++) {
                    int col = wn * 64 + nn * 8 + (lane & 3) * 2;
                    float2 o;
                    o.x = acc[m][nn][h * 2 + 0] * d;
                    o.y = acc[m][nn][h * 2 + 1] * d;
                    *(float2*)&g_h[(size_t)row * DHID + col] = o;
                }
            }
        }
    }
}

// ---------------------------------------------------------------------------
// scatter1 (segment sum): acc1[v] = h[v] + sum_{e: dst=v} h[src_e]
// One warp per node, float4 per lane (128 cols).
// ---------------------------------------------------------------------------
__global__ __launch_bounds__(256) void k_scatter1(int n) {
    int w = (blockIdx.x * blockDim.x + threadIdx.x) >> 5;
    int lane = threadIdx.x & 31;
    if (w >= n) return;
    int deg = g_degi[w];
    float4 acc = *(const float4*)&g_h[(size_t)w * DHID + lane * 4];
    int nb = min(deg, BCAP);
    for (int base = 0; base < nb; base += 32) {
        int cnt = min(nb - base, 32);
        int s = (lane < cnt) ? g_srcs[w * BCAP + base + lane] : 0;
        int e = 0;
        int src = __shfl_sync(0xffffffffu, s, 0);
        float4 v = *(const float4*)&g_h[(size_t)src * DHID + lane * 4];
        for (; e + 1 < cnt; e++) {
            int srcn = __shfl_sync(0xffffffffu, s, e + 1);
            float4 vn = *(const float4*)&g_h[(size_t)srcn * DHID + lane * 4];
            acc.x += v.x; acc.y += v.y; acc.z += v.z; acc.w += v.w;
            v = vn;
        }
        acc.x += v.x; acc.y += v.y; acc.z += v.z; acc.w += v.w;
    }
    if (deg > BCAP) {  // practically never; correctness fallback
        int oc = min(g_ovf_cnt, OVF_MAX);
        for (int i = 0; i < oc; i++) {
            int2 ed = g_ovf[i];
            if (ed.y == w) {
                float4 v = *(const float4*)&g_h[(size_t)ed.x * DHID + lane * 4];
                acc.x += v.x; acc.y += v.y; acc.z += v.z; acc.w += v.w;
            }
        }
    }
    *(float4*)&g_acc1[(size_t)w * DHID + lane * 4] = acc;
}

// ---------------------------------------------------------------------------
// GEMM2 (tf32 MMA): in[i][k] = relu(dinv[i]*acc1[i][k] + b1[k]);
//                   g_h2 = dinv * (in @ W2)
// ---------------------------------------------------------------------------
__global__ __launch_bounds__(256) void k_gemm2(const float* __restrict__ b1,
                                               const float* __restrict__ W,
                                               int n) {
    __shared__ unsigned xs[128][36];
    __shared__ unsigned ws[32][68];

    const int t = threadIdx.x;
    const int lane = t & 31;
    const int warp = t >> 5;
    const int wm = warp >> 1;
    const int wn = warp & 1;
    const int row0 = blockIdx.x * 128;

    float acc[2][4][4];
#pragma unroll
    for (int m = 0; m < 2; m++)
#pragma unroll
        for (int nn = 0; nn < 4; nn++)
#pragma unroll
            for (int j = 0; j < 4; j++) acc[m][nn][j] = 0.f;

    for (int kc = 0; kc < DHID; kc += 32) {
#pragma unroll
        for (int i = 0; i < 4; i++) {
            int idx = t + i * 256;
            int r = idx >> 3, c = (idx & 7) * 4;
            float4 v = make_float4(0.f, 0.f, 0.f, 0.f);
            if (row0 + r < n) {
                float d = dinv_of(row0 + r);
                float4 a4 = *(const float4*)&g_acc1[(size_t)(row0 + r) * DHID + kc + c];
                float4 b4 = *(const float4*)&b1[kc + c];
                v.x = fmaxf(d * a4.x + b4.x, 0.f);
                v.y = fmaxf(d * a4.y + b4.y, 0.f);
                v.z = fmaxf(d * a4.z + b4.z, 0.f);
                v.w = fmaxf(d * a4.w + b4.w, 0.f);
            }
            xs[r][c + 0] = f2tf(v.x); xs[r][c + 1] = f2tf(v.y);
            xs[r][c + 2] = f2tf(v.z); xs[r][c + 3] = f2tf(v.w);
        }
#pragma unroll
        for (int i = 0; i < 2; i++) {
            int idx = t + i * 256;
            int k = idx >> 4, c = (idx & 15) * 4;
            float4 v = *(const float4*)&W[(size_t)(kc + k) * DOUT + c];
            ws[k][c + 0] = f2tf(v.x); ws[k][c + 1] = f2tf(v.y);
            ws[k][c + 2] = f2tf(v.z); ws[k][c + 3] = f2tf(v.w);
        }
        __syncthreads();
#pragma unroll
        for (int ks = 0; ks < 4; ks++) {
            int k0 = ks * 8;
            unsigned a[2][4];
#pragma unroll
            for (int m = 0; m < 2; m++) {
                int r = wm * 32 + m * 16 + (lane >> 2);
                int kk = k0 + (lane & 3);
                a[m][0] = xs[r][kk];
                a[m][1] = xs[r + 8][kk];
                a[m][2] = xs[r][kk + 4];
                a[m][3] = xs[r + 8][kk + 4];
            }
#pragma unroll
            for (int nn = 0; nn < 4; nn++) {
                unsigned b[2];
                int c = wn * 32 + nn * 8 + (lane >> 2);
                b[0] = ws[k0 + (lane & 3)][c];
                b[1] = ws[k0 + (lane & 3) + 4][c];
                mma8(acc[0][nn], a[0], b);
                mma8(acc[1][nn], a[1], b);
            }
        }
        __syncthreads();
    }
#pragma unroll
    for (int m = 0; m < 2; m++) {
#pragma unroll
        for (int h = 0; h < 2; h++) {
            int row = row0 + wm * 32 + m * 16 + (lane >> 2) + h * 8;
            if (row < n) {
                float d = dinv_of(row);
#pragma unroll
                for (int nn = 0; nn < 4; nn++) {
                    int col = wn * 32 + nn * 8 + (lane & 3) * 2;
                    float2 o;
                    o.x = acc[m][nn][h * 2 + 0] * d;
                    o.y = acc[m][nn][h * 2 + 1] * d;
                    *(float2*)&g_h2[(size_t)row * DOUT + col] = o;
                }
            }
        }
    }
}

// ---------------------------------------------------------------------------
// scatter2 (segment sum): acc2[v] = h2[v] + sum h2[src]; float2 per lane (64 cols)
// ---------------------------------------------------------------------------
__global__ __launch_bounds__(256) void k_scatter2(int n) {
    int w = (blockIdx.x * blockDim.x + threadIdx.x) >> 5;
    int lane = threadIdx.x & 31;
    if (w >= n) return;
    int deg = g_degi[w];
    float2 acc = *(const float2*)&g_h2[(size_t)w * DOUT + lane * 2];
    int nb = min(deg, BCAP);
    for (int base = 0; base < nb; base += 32) {
        int cnt = min(nb - base, 32);
        int s = (lane < cnt) ? g_srcs[w * BCAP + base + lane] : 0;
        int e = 0;
        int src = __shfl_sync(0xffffffffu, s, 0);
        float2 v = *(const float2*)&g_h2[(size_t)src * DOUT + lane * 2];
        for (; e + 1 < cnt; e++) {
            int srcn = __shfl_sync(0xffffffffu, s, e + 1);
            float2 vn = *(const float2*)&g_h2[(size_t)srcn * DOUT + lane * 2];
            acc.x += v.x; acc.y += v.y;
            v = vn;
        }
        acc.x += v.x; acc.y += v.y;
    }
    if (deg > BCAP) {
        int oc = min(g_ovf_cnt, OVF_MAX);
        for (int i = 0; i < oc; i++) {
            int2 ed = g_ovf[i];
            if (ed.y == w) {
                float2 v = *(const float2*)&g_h2[(size_t)ed.x * DOUT + lane * 2];
                acc.x += v.x; acc.y += v.y;
            }
        }
    }
    *(float2*)&g_acc2[(size_t)w * DOUT + lane * 2] = acc;
}

// ---------------------------------------------------------------------------
// finalize: out = dinv * acc2 + b2
// ---------------------------------------------------------------------------
__global__ void k_final(const float* __restrict__ b2, float* __restrict__ out, int n) {
    int idx = blockIdx.x * blockDim.x + threadIdx.x;
    if (idx >= n * 16) return;
    int row = idx >> 4;
    int c = (idx & 15) * 4;
    float d = dinv_of(row);
    float4 a  = *(const float4*)&g_acc2[(size_t)row * DOUT + c];
    float4 bb = *(const float4*)&b2[c];
    float4 o = make_float4(d * a.x + bb.x, d * a.y + bb.y, d * a.z + bb.z, d * a.w + bb.w);
    *(float4*)&out[(size_t)idx * 4] = o;
}

extern "C" void kernel_launch(void* const* d_in, const int* in_sizes, int n_in,
                              void* d_out, int out_size) {
    const float* x  = (const float*)d_in[0];
    const void*  ei = d_in[1];
    const float* W1 = (const float*)d_in[2];
    const float* b1 = (const float*)d_in[3];
    const float* W2 = (const float*)d_in[4];
    const float* b2 = (const float*)d_in[5];
    float* out = (float*)d_out;

    const int n = in_sizes[0] / DIN;
    const int E = in_sizes[1] / 2;

    k_init<<<(n + 255) / 256, 256>>>((const unsigned int*)ei, n);
    k_convert<<<(E + 255) / 256, 256>>>(ei, E);

    k_gemm1<<<(n + 127) / 128, 256>>>(x, W1, n);
    k_scatter1<<<(n * 32 + 255) / 256, 256>>>(n);

    k_gemm2<<<(n + 127) / 128, 256>>>(b1, W2, n);
    k_scatter2<<<(n * 32 + 255) / 256, 256>>>(n);

    k_final<<<(n * 16 + 255) / 256, 256>>>(b2, out, n);
}

// round 4
// speedup vs baseline: 2.3009x; 1.1156x over previous
#include <cuda_runtime.h>
#include <cuda_fp16.h>

#define NMAX 50000
#define BCAP 64
#define OVF_MAX 4096
#define DIN 128
#define DHID 128
#define DOUT 64

__device__ int    g_degi[NMAX];            // in-degree (no self-loop)
__device__ int    g_srcs[NMAX * BCAP];     // bucketed src lists per dst
__device__ int2   g_ovf[OVF_MAX];          // overflow edges (src,dst)
__device__ int    g_ovf_cnt;
__device__ __half g_h[NMAX * DHID];        // fp16: dinv[i] * (x[i] @ W1)
__device__ float  g_acc1[NMAX * DHID];     // fp32 segment sums
__device__ __half g_h2[NMAX * DOUT];       // fp16: dinv[i] * (relu1[i] @ W2)
__device__ int    g_is64;

__device__ __forceinline__ unsigned f2tf(float f) {
    unsigned u;
    asm("cvt.rna.tf32.f32 %0, %1;" : "=r"(u) : "f"(f));
    return u;
}

__device__ __forceinline__ void mma8(float* c, const unsigned* a, const unsigned* b) {
    asm volatile(
        "mma.sync.aligned.m16n8k8.row.col.f32.tf32.tf32.f32 "
        "{%0,%1,%2,%3},{%4,%5,%6,%7},{%8,%9},{%0,%1,%2,%3};"
        : "+f"(c[0]), "+f"(c[1]), "+f"(c[2]), "+f"(c[3])
        : "r"(a[0]), "r"(a[1]), "r"(a[2]), "r"(a[3]), "r"(b[0]), "r"(b[1]));
}

__device__ __forceinline__ float dinv_of(int row) {
    return rsqrtf((float)(g_degi[row] + 1));
}

__device__ __forceinline__ float4 h4_to_f4(uint2 u) {
    float2 a = __half22float2(*(__half2*)&u.x);
    float2 b = __half22float2(*(__half2*)&u.y);
    return make_float4(a.x, a.y, b.x, b.y);
}

// ---------------------------------------------------------------------------
__global__ void k_init(const unsigned int* p, int n) {
    int i = blockIdx.x * blockDim.x + threadIdx.x;
    if (i < n) g_degi[i] = 0;
    if (i == 0) {
        g_ovf_cnt = 0;
        int ok = 1;
        for (int j = 0; j < 64; j++)
            if (p[2 * j + 1] != 0u) ok = 0;
        g_is64 = ok;
    }
}

__global__ void k_convert(const void* ei, int E) {
    int e = blockIdx.x * blockDim.x + threadIdx.x;
    if (e >= E) return;
    int src, dst;
    if (g_is64) {
        const long long* p = (const long long*)ei;
        src = (int)p[e]; dst = (int)p[E + e];
    } else {
        const int* p = (const int*)ei;
        src = p[e]; dst = p[E + e];
    }
    int slot = atomicAdd(&g_degi[dst], 1);
    if (slot < BCAP) {
        g_srcs[dst * BCAP + slot] = src;
    } else {
        int o = atomicAdd(&g_ovf_cnt, 1);
        if (o < OVF_MAX) g_ovf[o] = make_int2(src, dst);
    }
}

// ---------------------------------------------------------------------------
// GEMM1 (tf32 MMA): g_h[i][:] = fp16(dinv[i] * (x[i] @ W1))
// ---------------------------------------------------------------------------
__global__ __launch_bounds__(256) void k_gemm1(const float* __restrict__ x,
                                               const float* __restrict__ W,
                                               int n) {
    __shared__ unsigned xs[128][36];
    __shared__ unsigned ws[32][132];

    const int t = threadIdx.x;
    const int lane = t & 31;
    const int warp = t >> 5;
    const int wm = warp >> 1;
    const int wn = warp & 1;
    const int row0 = blockIdx.x * 128;

    float acc[2][8][4];
#pragma unroll
    for (int m = 0; m < 2; m++)
#pragma unroll
        for (int nn = 0; nn < 8; nn++)
#pragma unroll
            for (int j = 0; j < 4; j++) acc[m][nn][j] = 0.f;

    for (int kc = 0; kc < DIN; kc += 32) {
#pragma unroll
        for (int i = 0; i < 4; i++) {
            int idx = t + i * 256;
            int r = idx >> 3, c = (idx & 7) * 4;
            float4 v = make_float4(0.f, 0.f, 0.f, 0.f);
            if (row0 + r < n)
                v = *(const float4*)&x[(size_t)(row0 + r) * DIN + kc + c];
            xs[r][c + 0] = f2tf(v.x); xs[r][c + 1] = f2tf(v.y);
            xs[r][c + 2] = f2tf(v.z); xs[r][c + 3] = f2tf(v.w);
        }
#pragma unroll
        for (int i = 0; i < 4; i++) {
            int idx = t + i * 256;
            int k = idx >> 5, c = (idx & 31) * 4;
            float4 v = *(const float4*)&W[(size_t)(kc + k) * DHID + c];
            ws[k][c + 0] = f2tf(v.x); ws[k][c + 1] = f2tf(v.y);
            ws[k][c + 2] = f2tf(v.z); ws[k][c + 3] = f2tf(v.w);
        }
        __syncthreads();
#pragma unroll
        for (int ks = 0; ks < 4; ks++) {
            int k0 = ks * 8;
            unsigned a[2][4];
#pragma unroll
            for (int m = 0; m < 2; m++) {
                int r = wm * 32 + m * 16 + (lane >> 2);
                int kk = k0 + (lane & 3);
                a[m][0] = xs[r][kk];
                a[m][1] = xs[r + 8][kk];
                a[m][2] = xs[r][kk + 4];
                a[m][3] = xs[r + 8][kk + 4];
            }
#pragma unroll
            for (int nn = 0; nn < 8; nn++) {
                unsigned b[2];
                int c = wn * 64 + nn * 8 + (lane >> 2);
                b[0] = ws[k0 + (lane & 3)][c];
                b[1] = ws[k0 + (lane & 3) + 4][c];
                mma8(acc[0][nn], a[0], b);
                mma8(acc[1][nn], a[1], b);
            }
        }
        __syncthreads();
    }
#pragma unroll
    for (int m = 0; m < 2; m++) {
#pragma unroll
        for (int h = 0; h < 2; h++) {
            int row = row0 + wm * 32 + m * 16 + (lane >> 2) + h * 8;
            if (row < n) {
                float d = dinv_of(row);
#pragma unroll
                for (int nn = 0; nn < 8; nn++) {
                    int col = wn * 64 + nn * 8 + (lane & 3) * 2;
                    __half2 o = __floats2half2_rn(acc[m][nn][h * 2 + 0] * d,
                                                  acc[m][nn][h * 2 + 1] * d);
                    *(__half2*)&g_h[(size_t)row * DHID + col] = o;
                }
            }
        }
    }
}

// ---------------------------------------------------------------------------
// scatter1 (segment sum, fp16 gather -> fp32 acc): one warp per node,
// lane handles cols lane*4..lane*4+3 (8 bytes fp16).
// ---------------------------------------------------------------------------
__global__ __launch_bounds__(256) void k_scatter1(int n) {
    int w = (blockIdx.x * blockDim.x + threadIdx.x) >> 5;
    int lane = threadIdx.x & 31;
    if (w >= n) return;
    int deg = g_degi[w];

    float4 acc = h4_to_f4(*(const uint2*)&g_h[(size_t)w * DHID + lane * 4]);

    int nb = min(deg, BCAP);
    for (int base = 0; base < nb; base += 32) {
        int cnt = min(nb - base, 32);
        int s = (lane < cnt) ? g_srcs[w * BCAP + base + lane] : 0;
        int i = 0;
        for (; i + 4 <= cnt; i += 4) {
            int s0 = __shfl_sync(0xffffffffu, s, i);
            int s1 = __shfl_sync(0xffffffffu, s, i + 1);
            int s2 = __shfl_sync(0xffffffffu, s, i + 2);
            int s3 = __shfl_sync(0xffffffffu, s, i + 3);
            uint2 u0 = *(const uint2*)&g_h[(size_t)s0 * DHID + lane * 4];
            uint2 u1 = *(const uint2*)&g_h[(size_t)s1 * DHID + lane * 4];
            uint2 u2 = *(const uint2*)&g_h[(size_t)s2 * DHID + lane * 4];
            uint2 u3 = *(const uint2*)&g_h[(size_t)s3 * DHID + lane * 4];
            float4 v0 = h4_to_f4(u0), v1 = h4_to_f4(u1);
            float4 v2 = h4_to_f4(u2), v3 = h4_to_f4(u3);
            acc.x += v0.x + v1.x + v2.x + v3.x;
            acc.y += v0.y + v1.y + v2.y + v3.y;
            acc.z += v0.z + v1.z + v2.z + v3.z;
            acc.w += v0.w + v1.w + v2.w + v3.w;
        }
        for (; i < cnt; i++) {
            int s0 = __shfl_sync(0xffffffffu, s, i);
            float4 v = h4_to_f4(*(const uint2*)&g_h[(size_t)s0 * DHID + lane * 4]);
            acc.x += v.x; acc.y += v.y; acc.z += v.z; acc.w += v.w;
        }
    }
    if (deg > BCAP) {  // correctness fallback, practically never taken
        int oc = min(g_ovf_cnt, OVF_MAX);
        for (int i = 0; i < oc; i++) {
            int2 ed = g_ovf[i];
            if (ed.y == w) {
                float4 v = h4_to_f4(*(const uint2*)&g_h[(size_t)ed.x * DHID + lane * 4]);
                acc.x += v.x; acc.y += v.y; acc.z += v.z; acc.w += v.w;
            }
        }
    }
    *(float4*)&g_acc1[(size_t)w * DHID + lane * 4] = acc;
}

// ---------------------------------------------------------------------------
// GEMM2 (tf32 MMA): in = relu(dinv*acc1 + b1);  g_h2 = fp16(dinv * (in @ W2))
// ---------------------------------------------------------------------------
__global__ __launch_bounds__(256) void k_gemm2(const float* __restrict__ b1,
                                               const float* __restrict__ W,
                                               int n) {
    __shared__ unsigned xs[128][36];
    __shared__ unsigned ws[32][68];

    const int t = threadIdx.x;
    const int lane = t & 31;
    const int warp = t >> 5;
    const int wm = warp >> 1;
    const int wn = warp & 1;
    const int row0 = blockIdx.x * 128;

    float acc[2][4][4];
#pragma unroll
    for (int m = 0; m < 2; m++)
#pragma unroll
        for (int nn = 0; nn < 4; nn++)
#pragma unroll
            for (int j = 0; j < 4; j++) acc[m][nn][j] = 0.f;

    for (int kc = 0; kc < DHID; kc += 32) {
#pragma unroll
        for (int i = 0; i < 4; i++) {
            int idx = t + i * 256;
            int r = idx >> 3, c = (idx & 7) * 4;
            float4 v = make_float4(0.f, 0.f, 0.f, 0.f);
            if (row0 + r < n) {
                float d = dinv_of(row0 + r);
                float4 a4 = *(const float4*)&g_acc1[(size_t)(row0 + r) * DHID + kc + c];
                float4 b4 = *(const float4*)&b1[kc + c];
                v.x = fmaxf(d * a4.x + b4.x, 0.f);
                v.y = fmaxf(d * a4.y + b4.y, 0.f);
                v.z = fmaxf(d * a4.z + b4.z, 0.f);
                v.w = fmaxf(d * a4.w + b4.w, 0.f);
            }
            xs[r][c + 0] = f2tf(v.x); xs[r][c + 1] = f2tf(v.y);
            xs[r][c + 2] = f2tf(v.z); xs[r][c + 3] = f2tf(v.w);
        }
#pragma unroll
        for (int i = 0; i < 2; i++) {
            int idx = t + i * 256;
            int k = idx >> 4, c = (idx & 15) * 4;
            float4 v = *(const float4*)&W[(size_t)(kc + k) * DOUT + c];
            ws[k][c + 0] = f2tf(v.x); ws[k][c + 1] = f2tf(v.y);
            ws[k][c + 2] = f2tf(v.z); ws[k][c + 3] = f2tf(v.w);
        }
        __syncthreads();
#pragma unroll
        for (int ks = 0; ks < 4; ks++) {
            int k0 = ks * 8;
            unsigned a[2][4];
#pragma unroll
            for (int m = 0; m < 2; m++) {
                int r = wm * 32 + m * 16 + (lane >> 2);
                int kk = k0 + (lane & 3);
                a[m][0] = xs[r][kk];
                a[m][1] = xs[r + 8][kk];
                a[m][2] = xs[r][kk + 4];
                a[m][3] = xs[r + 8][kk + 4];
            }
#pragma unroll
            for (int nn = 0; nn < 4; nn++) {
                unsigned b[2];
                int c = wn * 32 + nn * 8 + (lane >> 2);
                b[0] = ws[k0 + (lane & 3)][c];
                b[1] = ws[k0 + (lane & 3) + 4][c];
                mma8(acc[0][nn], a[0], b);
                mma8(acc[1][nn], a[1], b);
            }
        }
        __syncthreads();
    }
#pragma unroll
    for (int m = 0; m < 2; m++) {
#pragma unroll
        for (int h = 0; h < 2; h++) {
            int row = row0 + wm * 32 + m * 16 + (lane >> 2) + h * 8;
            if (row < n) {
                float d = dinv_of(row);
#pragma unroll
                for (int nn = 0; nn < 4; nn++) {
                    int col = wn * 32 + nn * 8 + (lane & 3) * 2;
                    __half2 o = __floats2half2_rn(acc[m][nn][h * 2 + 0] * d,
                                                  acc[m][nn][h * 2 + 1] * d);
                    *(__half2*)&g_h2[(size_t)row * DOUT + col] = o;
                }
            }
        }
    }
}

// ---------------------------------------------------------------------------
// scatter2 + final (fused): out[v] = dinv[v] * (h2[v] + sum h2[src]) + b2
// one warp per node, lane handles 2 cols (half2 = 4B)
// ---------------------------------------------------------------------------
__global__ __launch_bounds__(256) void k_scatter2(const float* __restrict__ b2,
                                                  float* __restrict__ out, int n) {
    int w = (blockIdx.x * blockDim.x + threadIdx.x) >> 5;
    int lane = threadIdx.x & 31;
    if (w >= n) return;
    int deg = g_degi[w];

    float2 acc = __half22float2(*(const __half2*)&g_h2[(size_t)w * DOUT + lane * 2]);

    int nb = min(deg, BCAP);
    for (int base = 0; base < nb; base += 32) {
        int cnt = min(nb - base, 32);
        int s = (lane < cnt) ? g_srcs[w * BCAP + base + lane] : 0;
        int i = 0;
        for (; i + 4 <= cnt; i += 4) {
            int s0 = __shfl_sync(0xffffffffu, s, i);
            int s1 = __shfl_sync(0xffffffffu, s, i + 1);
            int s2 = __shfl_sync(0xffffffffu, s, i + 2);
            int s3 = __shfl_sync(0xffffffffu, s, i + 3);
            float2 v0 = __half22float2(*(const __half2*)&g_h2[(size_t)s0 * DOUT + lane * 2]);
            float2 v1 = __half22float2(*(const __half2*)&g_h2[(size_t)s1 * DOUT + lane * 2]);
            float2 v2 = __half22float2(*(const __half2*)&g_h2[(size_t)s2 * DOUT + lane * 2]);
            float2 v3 = __half22float2(*(const __half2*)&g_h2[(size_t)s3 * DOUT + lane * 2]);
            acc.x += v0.x + v1.x + v2.x + v3.x;
            acc.y += v0.y + v1.y + v2.y + v3.y;
        }
        for (; i < cnt; i++) {
            int s0 = __shfl_sync(0xffffffffu, s, i);
            float2 v = __half22float2(*(const __half2*)&g_h2[(size_t)s0 * DOUT + lane * 2]);
            acc.x += v.x; acc.y += v.y;
        }
    }
    if (deg > BCAP) {
        int oc = min(g_ovf_cnt, OVF_MAX);
        for (int i = 0; i < oc; i++) {
            int2 ed = g_ovf[i];
            if (ed.y == w) {
                float2 v = __half22float2(*(const __half2*)&g_h2[(size_t)ed.x * DOUT + lane * 2]);
                acc.x += v.x; acc.y += v.y;
            }
        }
    }
    float d = dinv_of(w);
    float2 bb = *(const float2*)&b2[lane * 2];
    float2 o = make_float2(d * acc.x + bb.x, d * acc.y + bb.y);
    *(float2*)&out[(size_t)w * DOUT + lane * 2] = o;
}

extern "C" void kernel_launch(void* const* d_in, const int* in_sizes, int n_in,
                              void* d_out, int out_size) {
    const float* x  = (const float*)d_in[0];
    const void*  ei = d_in[1];
    const float* W1 = (const float*)d_in[2];
    const float* b1 = (const float*)d_in[3];
    const float* W2 = (const float*)d_in[4];
    const float* b2 = (const float*)d_in[5];
    float* out = (float*)d_out;

    const int n = in_sizes[0] / DIN;
    const int E = in_sizes[1] / 2;

    k_init<<<(n + 255) / 256, 256>>>((const unsigned int*)ei, n);
    k_convert<<<(E + 255) / 256, 256>>>(ei, E);

    k_gemm1<<<(n + 127) / 128, 256>>>(x, W1, n);
    k_scatter1<<<(n * 32 + 255) / 256, 256>>>(n);

    k_gemm2<<<(n + 127) / 128, 256>>>(b1, W2, n);
    k_scatter2<<<(n * 32 + 255) / 256, 256>>>(b2, out, n);
}

// round 5
// speedup vs baseline: 2.3424x; 1.0180x over previous
#include <cuda_runtime.h>
#include <cuda_fp16.h>

#define NMAX 50000
#define BCAP 64
#define OVF_MAX 4096
#define DIN 128
#define DHID 128
#define DOUT 64

__device__ int    g_degi[NMAX];
__device__ int    g_srcs[NMAX * BCAP];
__device__ int2   g_ovf[OVF_MAX];
__device__ int    g_ovf_cnt;
__device__ __half g_h[NMAX * DHID];
__device__ float  g_acc1[NMAX * DHID];
__device__ __half g_h2[NMAX * DOUT];
__device__ int    g_is64;

__device__ __forceinline__ unsigned f2tf(float f) {
    unsigned u;
    asm("cvt.rna.tf32.f32 %0, %1;" : "=r"(u) : "f"(f));
    return u;
}

__device__ __forceinline__ void mma8(float* c, const unsigned* a, const unsigned* b) {
    asm volatile(
        "mma.sync.aligned.m16n8k8.row.col.f32.tf32.tf32.f32 "
        "{%0,%1,%2,%3},{%4,%5,%6,%7},{%8,%9},{%0,%1,%2,%3};"
        : "+f"(c[0]), "+f"(c[1]), "+f"(c[2]), "+f"(c[3])
        : "r"(a[0]), "r"(a[1]), "r"(a[2]), "r"(a[3]), "r"(b[0]), "r"(b[1]));
}

__device__ __forceinline__ float dinv_of(int row) {
    return rsqrtf((float)(g_degi[row] + 1));
}

// add one edge payload (8 fp16) to fp32 acc
__device__ __forceinline__ void acc8_one(float* acc, uint4 a) {
    float2 f0 = __half22float2(*(__half2*)&a.x);
    float2 f1 = __half22float2(*(__half2*)&a.y);
    float2 f2 = __half22float2(*(__half2*)&a.z);
    float2 f3 = __half22float2(*(__half2*)&a.w);
    acc[0] += f0.x; acc[1] += f0.y; acc[2] += f1.x; acc[3] += f1.y;
    acc[4] += f2.x; acc[5] += f2.y; acc[6] += f3.x; acc[7] += f3.y;
}

// add two edge payloads: pairwise fp16 add, then convert once
__device__ __forceinline__ void acc8_pair(float* acc, uint4 a, uint4 b) {
    __half2 p0 = __hadd2(*(__half2*)&a.x, *(__half2*)&b.x);
    __half2 p1 = __hadd2(*(__half2*)&a.y, *(__half2*)&b.y);
    __half2 p2 = __hadd2(*(__half2*)&a.z, *(__half2*)&b.z);
    __half2 p3 = __hadd2(*(__half2*)&a.w, *(__half2*)&b.w);
    float2 f0 = __half22float2(p0), f1 = __half22float2(p1);
    float2 f2 = __half22float2(p2), f3 = __half22float2(p3);
    acc[0] += f0.x; acc[1] += f0.y; acc[2] += f1.x; acc[3] += f1.y;
    acc[4] += f2.x; acc[5] += f2.y; acc[6] += f3.x; acc[7] += f3.y;
}

// ---------------------------------------------------------------------------
__global__ void k_init(const unsigned int* p, int n) {
    int i = blockIdx.x * blockDim.x + threadIdx.x;
    if (i < n) g_degi[i] = 0;
    if (i == 0) {
        g_ovf_cnt = 0;
        int ok = 1;
        for (int j = 0; j < 64; j++)
            if (p[2 * j + 1] != 0u) ok = 0;
        g_is64 = ok;
    }
}

__global__ void k_convert(const void* ei, int E) {
    int e = blockIdx.x * blockDim.x + threadIdx.x;
    if (e >= E) return;
    int src, dst;
    if (g_is64) {
        const long long* p = (const long long*)ei;
        src = (int)p[e]; dst = (int)p[E + e];
    } else {
        const int* p = (const int*)ei;
        src = p[e]; dst = p[E + e];
    }
    int slot = atomicAdd(&g_degi[dst], 1);
    if (slot < BCAP) {
        g_srcs[dst * BCAP + slot] = src;
    } else {
        int o = atomicAdd(&g_ovf_cnt, 1);
        if (o < OVF_MAX) g_ovf[o] = make_int2(src, dst);
    }
}

// ---------------------------------------------------------------------------
// GEMM1 (tf32 MMA): g_h[i][:] = fp16(dinv[i] * (x[i] @ W1))
// ---------------------------------------------------------------------------
__global__ __launch_bounds__(256) void k_gemm1(const float* __restrict__ x,
                                               const float* __restrict__ W,
                                               int n) {
    __shared__ unsigned xs[128][36];
    __shared__ unsigned ws[32][132];

    const int t = threadIdx.x;
    const int lane = t & 31;
    const int warp = t >> 5;
    const int wm = warp >> 1;
    const int wn = warp & 1;
    const int row0 = blockIdx.x * 128;

    float acc[2][8][4];
#pragma unroll
    for (int m = 0; m < 2; m++)
#pragma unroll
        for (int nn = 0; nn < 8; nn++)
#pragma unroll
            for (int j = 0; j < 4; j++) acc[m][nn][j] = 0.f;

    for (int kc = 0; kc < DIN; kc += 32) {
#pragma unroll
        for (int i = 0; i < 4; i++) {
            int idx = t + i * 256;
            int r = idx >> 3, c = (idx & 7) * 4;
            float4 v = make_float4(0.f, 0.f, 0.f, 0.f);
            if (row0 + r < n)
                v = *(const float4*)&x[(size_t)(row0 + r) * DIN + kc + c];
            xs[r][c + 0] = f2tf(v.x); xs[r][c + 1] = f2tf(v.y);
            xs[r][c + 2] = f2tf(v.z); xs[r][c + 3] = f2tf(v.w);
        }
#pragma unroll
        for (int i = 0; i < 4; i++) {
            int idx = t + i * 256;
            int k = idx >> 5, c = (idx & 31) * 4;
            float4 v = *(const float4*)&W[(size_t)(kc + k) * DHID + c];
            ws[k][c + 0] = f2tf(v.x); ws[k][c + 1] = f2tf(v.y);
            ws[k][c + 2] = f2tf(v.z); ws[k][c + 3] = f2tf(v.w);
        }
        __syncthreads();
#pragma unroll
        for (int ks = 0; ks < 4; ks++) {
            int k0 = ks * 8;
            unsigned a[2][4];
#pragma unroll
            for (int m = 0; m < 2; m++) {
                int r = wm * 32 + m * 16 + (lane >> 2);
                int kk = k0 + (lane & 3);
                a[m][0] = xs[r][kk];
                a[m][1] = xs[r + 8][kk];
                a[m][2] = xs[r][kk + 4];
                a[m][3] = xs[r + 8][kk + 4];
            }
#pragma unroll
            for (int nn = 0; nn < 8; nn++) {
                unsigned b[2];
                int c = wn * 64 + nn * 8 + (lane >> 2);
                b[0] = ws[k0 + (lane & 3)][c];
                b[1] = ws[k0 + (lane & 3) + 4][c];
                mma8(acc[0][nn], a[0], b);
                mma8(acc[1][nn], a[1], b);
            }
        }
        __syncthreads();
    }
#pragma unroll
    for (int m = 0; m < 2; m++) {
#pragma unroll
        for (int h = 0; h < 2; h++) {
            int row = row0 + wm * 32 + m * 16 + (lane >> 2) + h * 8;
            if (row < n) {
                float d = dinv_of(row);
#pragma unroll
                for (int nn = 0; nn < 8; nn++) {
                    int col = wn * 64 + nn * 8 + (lane & 3) * 2;
                    __half2 o = __floats2half2_rn(acc[m][nn][h * 2 + 0] * d,
                                                  acc[m][nn][h * 2 + 1] * d);
                    *(__half2*)&g_h[(size_t)row * DHID + col] = o;
                }
            }
        }
    }
}

// ---------------------------------------------------------------------------
// scatter1: 2 nodes per warp, 16 lanes each, LDG.128 (8 fp16 cols per lane).
// acc1[v] = h[v] + sum_{e: dst=v} h[src_e]   (fp32 accumulate, pairwise fp16 add)
// ---------------------------------------------------------------------------
__global__ __launch_bounds__(256) void k_scatter1(int n) {
    int gw = (blockIdx.x * blockDim.x + threadIdx.x) >> 5;   // warp id
    int lane = threadIdx.x & 31;
    int half = lane >> 4;
    int sub  = lane & 15;
    int node = gw * 2 + half;
    if (node >= n) return;
    unsigned gmask = 0xFFFFu << (half * 16);
    int deg = g_degi[node];

    float acc[8];
    acc8_one(acc - 0, make_uint4(0, 0, 0, 0));  // placeholder avoided below
#pragma unroll
    for (int j = 0; j < 8; j++) acc[j] = 0.f;
    acc8_one(acc, *(const uint4*)&g_h[(size_t)node * DHID + sub * 8]);

    int nb = min(deg, BCAP);
    for (int base = 0; base < nb; base += 16) {
        int cnt = min(nb - base, 16);
        int s = (sub < cnt) ? g_srcs[node * BCAP + base + sub] : 0;
        int i = 0;
        for (; i + 2 <= cnt; i += 2) {
            int s0 = __shfl_sync(gmask, s, half * 16 + i);
            int s1 = __shfl_sync(gmask, s, half * 16 + i + 1);
            uint4 a = *(const uint4*)&g_h[(size_t)s0 * DHID + sub * 8];
            uint4 b = *(const uint4*)&g_h[(size_t)s1 * DHID + sub * 8];
            acc8_pair(acc, a, b);
        }
        if (i < cnt) {
            int s0 = __shfl_sync(gmask, s, half * 16 + i);
            acc8_one(acc, *(const uint4*)&g_h[(size_t)s0 * DHID + sub * 8]);
        }
    }
    if (deg > BCAP) {  // correctness fallback, practically never taken
        int oc = min(g_ovf_cnt, OVF_MAX);
        for (int i = 0; i < oc; i++) {
            int2 ed = g_ovf[i];
            if (ed.y == node)
                acc8_one(acc, *(const uint4*)&g_h[(size_t)ed.x * DHID + sub * 8]);
        }
    }
    *(float4*)&g_acc1[(size_t)node * DHID + sub * 8]     = make_float4(acc[0], acc[1], acc[2], acc[3]);
    *(float4*)&g_acc1[(size_t)node * DHID + sub * 8 + 4] = make_float4(acc[4], acc[5], acc[6], acc[7]);
}

// ---------------------------------------------------------------------------
// GEMM2 (tf32 MMA): in = relu(dinv*acc1 + b1);  g_h2 = fp16(dinv * (in @ W2))
// ---------------------------------------------------------------------------
__global__ __launch_bounds__(256) void k_gemm2(const float* __restrict__ b1,
                                               const float* __restrict__ W,
                                               int n) {
    __shared__ unsigned xs[128][36];
    __shared__ unsigned ws[32][68];

    const int t = threadIdx.x;
    const int lane = t & 31;
    const int warp = t >> 5;
    const int wm = warp >> 1;
    const int wn = warp & 1;
    const int row0 = blockIdx.x * 128;

    float acc[2][4][4];
#pragma unroll
    for (int m = 0; m < 2; m++)
#pragma unroll
        for (int nn = 0; nn < 4; nn++)
#pragma unroll
            for (int j = 0; j < 4; j++) acc[m][nn][j] = 0.f;

    for (int kc = 0; kc < DHID; kc += 32) {
#pragma unroll
        for (int i = 0; i < 4; i++) {
            int idx = t + i * 256;
            int r = idx >> 3, c = (idx & 7) * 4;
            float4 v = make_float4(0.f, 0.f, 0.f, 0.f);
            if (row0 + r < n) {
                float d = dinv_of(row0 + r);
                float4 a4 = *(const float4*)&g_acc1[(size_t)(row0 + r) * DHID + kc + c];
                float4 b4 = *(const float4*)&b1[kc + c];
                v.x = fmaxf(d * a4.x + b4.x, 0.f);
                v.y = fmaxf(d * a4.y + b4.y, 0.f);
                v.z = fmaxf(d * a4.z + b4.z, 0.f);
                v.w = fmaxf(d * a4.w + b4.w, 0.f);
            }
            xs[r][c + 0] = f2tf(v.x); xs[r][c + 1] = f2tf(v.y);
            xs[r][c + 2] = f2tf(v.z); xs[r][c + 3] = f2tf(v.w);
        }
#pragma unroll
        for (int i = 0; i < 2; i++) {
            int idx = t + i * 256;
            int k = idx >> 4, c = (idx & 15) * 4;
            float4 v = *(const float4*)&W[(size_t)(kc + k) * DOUT + c];
            ws[k][c + 0] = f2tf(v.x); ws[k][c + 1] = f2tf(v.y);
            ws[k][c + 2] = f2tf(v.z); ws[k][c + 3] = f2tf(v.w);
        }
        __syncthreads();
#pragma unroll
        for (int ks = 0; ks < 4; ks++) {
            int k0 = ks * 8;
            unsigned a[2][4];
#pragma unroll
            for (int m = 0; m < 2; m++) {
                int r = wm * 32 + m * 16 + (lane >> 2);
                int kk = k0 + (lane & 3);
                a[m][0] = xs[r][kk];
                a[m][1] = xs[r + 8][kk];
                a[m][2] = xs[r][kk + 4];
                a[m][3] = xs[r + 8][kk + 4];
            }
#pragma unroll
            for (int nn = 0; nn < 4; nn++) {
                unsigned b[2];
                int c = wn * 32 + nn * 8 + (lane >> 2);
                b[0] = ws[k0 + (lane & 3)][c];
                b[1] = ws[k0 + (lane & 3) + 4][c];
                mma8(acc[0][nn], a[0], b);
                mma8(acc[1][nn], a[1], b);
            }
        }
        __syncthreads();
    }
#pragma unroll
    for (int m = 0; m < 2; m++) {
#pragma unroll
        for (int h = 0; h < 2; h++) {
            int row = row0 + wm * 32 + m * 16 + (lane >> 2) + h * 8;
            if (row < n) {
                float d = dinv_of(row);
#pragma unroll
                for (int nn = 0; nn < 4; nn++) {
                    int col = wn * 32 + nn * 8 + (lane & 3) * 2;
                    __half2 o = __floats2half2_rn(acc[m][nn][h * 2 + 0] * d,
                                                  acc[m][nn][h * 2 + 1] * d);
                    *(__half2*)&g_h2[(size_t)row * DOUT + col] = o;
                }
            }
        }
    }
}

// ---------------------------------------------------------------------------
// scatter2 + final: 4 nodes per warp, 8 lanes each, LDG.128.
// out[v] = dinv[v] * (h2[v] + sum h2[src]) + b2
// ---------------------------------------------------------------------------
__global__ __launch_bounds__(256) void k_scatter2(const float* __restrict__ b2,
                                                  float* __restrict__ out, int n) {
    int gw = (blockIdx.x * blockDim.x + threadIdx.x) >> 5;
    int lane = threadIdx.x & 31;
    int q   = lane >> 3;
    int sub = lane & 7;
    int node = gw * 4 + q;
    if (node >= n) return;
    unsigned gmask = 0xFFu << (q * 8);
    int deg = g_degi[node];

    float acc[8];
#pragma unroll
    for (int j = 0; j < 8; j++) acc[j] = 0.f;
    acc8_one(acc, *(const uint4*)&g_h2[(size_t)node * DOUT + sub * 8]);

    int nb = min(deg, BCAP);
    for (int base = 0; base < nb; base += 8) {
        int cnt = min(nb - base, 8);
        int s = (sub < cnt) ? g_srcs[node * BCAP + base + sub] : 0;
        int i = 0;
        for (; i + 2 <= cnt; i += 2) {
            int s0 = __shfl_sync(gmask, s, q * 8 + i);
            int s1 = __shfl_sync(gmask, s, q * 8 + i + 1);
            uint4 a = *(const uint4*)&g_h2[(size_t)s0 * DOUT + sub * 8];
            uint4 b = *(const uint4*)&g_h2[(size_t)s1 * DOUT + sub * 8];
            acc8_pair(acc, a, b);
        }
        if (i < cnt) {
            int s0 = __shfl_sync(gmask, s, q * 8 + i);
            acc8_one(acc, *(const uint4*)&g_h2[(size_t)s0 * DOUT + sub * 8]);
        }
    }
    if (deg > BCAP) {
        int oc = min(g_ovf_cnt, OVF_MAX);
        for (int i = 0; i < oc; i++) {
            int2 ed = g_ovf[i];
            if (ed.y == node)
                acc8_one(acc, *(const uint4*)&g_h2[(size_t)ed.x * DOUT + sub * 8]);
        }
    }
    float d = dinv_of(node);
    float4 b0 = *(const float4*)&b2[sub * 8];
    float4 b1v = *(const float4*)&b2[sub * 8 + 4];
    float4 o0 = make_float4(d * acc[0] + b0.x, d * acc[1] + b0.y,
                            d * acc[2] + b0.z, d * acc[3] + b0.w);
    float4 o1 = make_float4(d * acc[4] + b1v.x, d * acc[5] + b1v.y,
                            d * acc[6] + b1v.z, d * acc[7] + b1v.w);
    *(float4*)&out[(size_t)node * DOUT + sub * 8]     = o0;
    *(float4*)&out[(size_t)node * DOUT + sub * 8 + 4] = o1;
}

extern "C" void kernel_launch(void* const* d_in, const int* in_sizes, int n_in,
                              void* d_out, int out_size) {
    const float* x  = (const float*)d_in[0];
    const void*  ei = d_in[1];
    const float* W1 = (const float*)d_in[2];
    const float* b1 = (const float*)d_in[3];
    const float* W2 = (const float*)d_in[4];
    const float* b2 = (const float*)d_in[5];
    float* out = (float*)d_out;

    const int n = in_sizes[0] / DIN;
    const int E = in_sizes[1] / 2;

    k_init<<<(n + 255) / 256, 256>>>((const unsigned int*)ei, n);
    k_convert<<<(E + 255) / 256, 256>>>(ei, E);

    k_gemm1<<<(n + 127) / 128, 256>>>(x, W1, n);
    int warps1 = (n + 1) / 2;
    k_scatter1<<<(warps1 * 32 + 255) / 256, 256>>>(n);

    k_gemm2<<<(n + 127) / 128, 256>>>(b1, W2, n);
    int warps2 = (n + 3) / 4;
    k_scatter2<<<(warps2 * 32 + 255) / 256, 256>>>(b2, out, n);
}